// round 2
// baseline (speedup 1.0000x reference)
#include <cuda_runtime.h>
#include <math.h>

#define N_NODES  50000
#define N_EDGES  800000
#define N_GRAPHS 1000
#define F_INPUT  128
#define HID      64
#define OUT_F    16
#define BN_EPS   1e-5f

// ---------------- scratch (static device globals; no allocation) ------------
__device__ float g_B0[N_NODES * HID];      // v / h_prev buffer
__device__ float g_B1[N_NODES * HID];      // t (transformed features)
__device__ float g_B2[N_NODES * HID];      // a (aggregation accumulator)
__device__ float g_stats[3 * 2 * HID];     // per-layer sum, sumsq
__device__ float g_scale[3 * HID];         // folded BN scale
__device__ float g_shift[3 * HID];         // folded BN shift
__device__ float g_pooled[N_GRAPHS * HID]; // segment max

// ---------------- helpers ---------------------------------------------------
__device__ __forceinline__ void atomicMaxF(float* addr, float val) {
    if (val >= 0.f) atomicMax((int*)addr, __float_as_int(val));
    else            atomicMin((unsigned int*)addr, __float_as_uint(val));
}

// ---------------- init: zero BN stats, pooled = -inf ------------------------
__global__ void init_kernel() {
    int i = blockIdx.x * blockDim.x + threadIdx.x;
    if (i < 3 * 2 * HID) g_stats[i] = 0.f;
    if (i < N_GRAPHS * HID) g_pooled[i] = -INFINITY;
}

// ---------------- gemm1: t = (affine(h)) @ w1 ; write to B1 and B2 ----------
// AFF=false: h comes from h_in (layer 0 input x). AFF=true: h = g_B0 with
// previous layer's folded BN affine applied on load.
template <int IN_F, bool AFF>
__global__ void __launch_bounds__(256) gemm1_kernel(
    const float* __restrict__ h_in, const float* __restrict__ w, int prev_layer)
{
    __shared__ float w_sh[IN_F * HID];
    __shared__ float h_sh[8 * IN_F];
    int tid = threadIdx.x;

    for (int i = tid; i < IN_F * HID / 4; i += 256)
        ((float4*)w_sh)[i] = ((const float4*)w)[i];

    const float* h = AFF ? g_B0 : h_in;
    const float* scale = g_scale + prev_layer * HID;
    const float* shift = g_shift + prev_layer * HID;

    int rowbase = blockIdx.x * 8;
    const float4* hrow4 = (const float4*)(h + (long)rowbase * IN_F);
    for (int i = tid; i < 8 * IN_F / 4; i += 256) {
        float4 v = hrow4[i];
        if (AFF) {
            int k = (i * 4) % IN_F;
            v.x = v.x * scale[k + 0] + shift[k + 0];
            v.y = v.y * scale[k + 1] + shift[k + 1];
            v.z = v.z * scale[k + 2] + shift[k + 2];
            v.w = v.w * scale[k + 3] + shift[k + 3];
        }
        ((float4*)h_sh)[i] = v;
    }
    __syncthreads();

    int warp = tid >> 5, lane = tid & 31;
    const float* hr = h_sh + warp * IN_F;
    float acc0 = 0.f, acc1 = 0.f;
#pragma unroll 8
    for (int k = 0; k < IN_F; k++) {
        float hv = hr[k];
        acc0 += hv * w_sh[k * HID + lane];
        acc1 += hv * w_sh[k * HID + lane + 32];
    }
    int row = rowbase + warp;
    g_B1[row * HID + lane]      = acc0;
    g_B1[row * HID + lane + 32] = acc1;
    g_B2[row * HID + lane]      = acc0;   // self term (eps=0 GIN)
    g_B2[row * HID + lane + 32] = acc1;
}

// ---------------- edge scatter: B2[dst] += B1[src] --------------------------
__global__ void __launch_bounds__(256) edge_kernel(const int* __restrict__ ei)
{
    int idx = blockIdx.x * blockDim.x + threadIdx.x; // N_EDGES*8 threads
    int e = idx >> 3;
    if (e >= N_EDGES) return;
    int c = (idx & 7) * 8;
    int s = __ldg(&ei[e]);
    int d = __ldg(&ei[N_EDGES + e]);
    const float4* tp = (const float4*)(g_B1 + (long)s * HID + c);
    float4 v0 = __ldg(tp);
    float4 v1 = __ldg(tp + 1);
    float* ap = g_B2 + (long)d * HID + c;
    atomicAdd(ap + 0, v0.x); atomicAdd(ap + 1, v0.y);
    atomicAdd(ap + 2, v0.z); atomicAdd(ap + 3, v0.w);
    atomicAdd(ap + 4, v1.x); atomicAdd(ap + 5, v1.y);
    atomicAdd(ap + 6, v1.z); atomicAdd(ap + 7, v1.w);
}

// ---------------- gemm2: u=relu(B2+b1); v=relu(u@w2+b2) -> B0; stats --------
__global__ void __launch_bounds__(256) gemm2_kernel(
    const float* __restrict__ b1, const float* __restrict__ w2,
    const float* __restrict__ b2, int layer)
{
    __shared__ float w_sh[HID * HID];
    __shared__ float u_sh[8 * HID];
    __shared__ float s_sum[HID];
    __shared__ float s_sq[HID];
    int tid = threadIdx.x;

    for (int i = tid; i < HID * HID / 4; i += 256)
        ((float4*)w_sh)[i] = ((const float4*)w2)[i];
    if (tid < HID) { s_sum[tid] = 0.f; s_sq[tid] = 0.f; }

    int rowbase = blockIdx.x * 8;
    const float4* arow4 = (const float4*)(g_B2 + (long)rowbase * HID);
    for (int i = tid; i < 8 * HID / 4; i += 256) {
        float4 v = arow4[i];
        int k = (i * 4) % HID;
        v.x = fmaxf(v.x + b1[k + 0], 0.f);
        v.y = fmaxf(v.y + b1[k + 1], 0.f);
        v.z = fmaxf(v.z + b1[k + 2], 0.f);
        v.w = fmaxf(v.w + b1[k + 3], 0.f);
        ((float4*)u_sh)[i] = v;
    }
    __syncthreads();

    int warp = tid >> 5, lane = tid & 31;
    const float* ur = u_sh + warp * HID;
    float acc0 = b2[lane], acc1 = b2[lane + 32];
#pragma unroll 8
    for (int k = 0; k < HID; k++) {
        float uv = ur[k];
        acc0 += uv * w_sh[k * HID + lane];
        acc1 += uv * w_sh[k * HID + lane + 32];
    }
    acc0 = fmaxf(acc0, 0.f);
    acc1 = fmaxf(acc1, 0.f);
    int row = rowbase + warp;
    g_B0[row * HID + lane]      = acc0;
    g_B0[row * HID + lane + 32] = acc1;

    atomicAdd(&s_sum[lane], acc0);       atomicAdd(&s_sq[lane], acc0 * acc0);
    atomicAdd(&s_sum[lane + 32], acc1);  atomicAdd(&s_sq[lane + 32], acc1 * acc1);
    __syncthreads();
    float* stats = g_stats + layer * 2 * HID;
    if (tid < HID) {
        atomicAdd(&stats[tid], s_sum[tid]);
        atomicAdd(&stats[HID + tid], s_sq[tid]);
    }
}

// ---------------- BN finalize: fold into scale/shift ------------------------
__global__ void bn_finalize_kernel(const float* __restrict__ gamma,
                                   const float* __restrict__ beta, int layer)
{
    int c = threadIdx.x;
    if (c >= HID) return;
    const float* stats = g_stats + layer * 2 * HID;
    float inv_n = 1.f / (float)N_NODES;
    float mu  = stats[c] * inv_n;
    float var = stats[HID + c] * inv_n - mu * mu;
    float s = gamma[c] * rsqrtf(var + BN_EPS);
    g_scale[layer * HID + c] = s;
    g_shift[layer * HID + c] = beta[c] - mu * s;
}

// ---------------- pool: segment max of affine(B0) ---------------------------
__global__ void __launch_bounds__(256) pool_kernel(const int* __restrict__ batch)
{
    int idx = blockIdx.x * blockDim.x + threadIdx.x; // N_NODES*32
    int node = idx >> 5;
    if (node >= N_NODES) return;
    int lane = idx & 31;
    int g = __ldg(&batch[node]);
    const float* scale = g_scale + 2 * HID;
    const float* shift = g_shift + 2 * HID;
    float p0 = g_B0[node * HID + lane]      * scale[lane]      + shift[lane];
    float p1 = g_B0[node * HID + lane + 32] * scale[lane + 32] + shift[lane + 32];
    atomicMaxF(&g_pooled[g * HID + lane], p0);
    atomicMaxF(&g_pooled[g * HID + lane + 32], p1);
}

// ---------------- head: relu(pooled@lin1+b1)@lin2+b2 ------------------------
__global__ void __launch_bounds__(128) head_kernel(
    const float* __restrict__ lin1_w, const float* __restrict__ lin1_b,
    const float* __restrict__ lin2_w, const float* __restrict__ lin2_b,
    float* __restrict__ out)
{
    __shared__ float w1_sh[HID * HID];
    __shared__ float w2_sh[HID * OUT_F];
    __shared__ float p_sh[4][HID];
    __shared__ float h_sh[4][HID];
    int tid = threadIdx.x, warp = tid >> 5, lane = tid & 31;

    for (int i = tid; i < HID * HID / 4; i += 128)
        ((float4*)w1_sh)[i] = ((const float4*)lin1_w)[i];
    for (int i = tid; i < HID * OUT_F / 4; i += 128)
        ((float4*)w2_sh)[i] = ((const float4*)lin2_w)[i];

    int g = blockIdx.x * 4 + warp;
    float p0 = g_pooled[g * HID + lane];
    float p1 = g_pooled[g * HID + lane + 32];
    if (!isfinite(p0)) p0 = 0.f;
    if (!isfinite(p1)) p1 = 0.f;
    p_sh[warp][lane] = p0;
    p_sh[warp][lane + 32] = p1;
    __syncthreads();

    float acc0 = lin1_b[lane], acc1 = lin1_b[lane + 32];
#pragma unroll 8
    for (int k = 0; k < HID; k++) {
        float pv = p_sh[warp][k];
        acc0 += pv * w1_sh[k * HID + lane];
        acc1 += pv * w1_sh[k * HID + lane + 32];
    }
    h_sh[warp][lane]      = fmaxf(acc0, 0.f);
    h_sh[warp][lane + 32] = fmaxf(acc1, 0.f);
    __syncwarp();

    if (lane < OUT_F) {
        float acc = lin2_b[lane];
#pragma unroll 8
        for (int k = 0; k < HID; k++)
            acc += h_sh[warp][k] * w2_sh[k * OUT_F + lane];
        out[g * OUT_F + lane] = acc;
    }
}

// ---------------- launch ----------------------------------------------------
extern "C" void kernel_launch(void* const* d_in, const int* in_sizes, int n_in,
                              void* d_out, int out_size)
{
    const float* x     = (const float*)d_in[0];
    const int*   ei    = (const int*)d_in[1];    // int32 (JAX x64 disabled)
    const int*   batch = (const int*)d_in[2];
    const float* l0_w1 = (const float*)d_in[3];
    const float* l0_b1 = (const float*)d_in[4];
    const float* l0_w2 = (const float*)d_in[5];
    const float* l0_b2 = (const float*)d_in[6];
    const float* l0_g  = (const float*)d_in[7];
    const float* l0_be = (const float*)d_in[8];
    const float* ws1   = (const float*)d_in[9];
    const float* bs1   = (const float*)d_in[10];
    const float* ws2   = (const float*)d_in[11];
    const float* bs2   = (const float*)d_in[12];
    const float* gms   = (const float*)d_in[13];
    const float* bts   = (const float*)d_in[14];
    const float* lin1w = (const float*)d_in[15];
    const float* lin1b = (const float*)d_in[16];
    const float* lin2w = (const float*)d_in[17];
    const float* lin2b = (const float*)d_in[18];
    float* out = (float*)d_out;

    const int GEMM_BLOCKS = N_NODES / 8;               // 6250
    const int EDGE_BLOCKS = (N_EDGES * 8) / 256;       // 25000
    const int POOL_BLOCKS = (N_NODES * 32) / 256;      // 6250

    init_kernel<<<(N_GRAPHS * HID + 255) / 256, 256>>>();

    // ---- layer 0 (128 -> 64), no input affine ----
    gemm1_kernel<F_INPUT, false><<<GEMM_BLOCKS, 256>>>(x, l0_w1, 0);
    edge_kernel<<<EDGE_BLOCKS, 256>>>(ei);
    gemm2_kernel<<<GEMM_BLOCKS, 256>>>(l0_b1, l0_w2, l0_b2, 0);
    bn_finalize_kernel<<<1, 64>>>(l0_g, l0_be, 0);

    // ---- layer 1 (64 -> 64), applies layer-0 BN on load ----
    gemm1_kernel<HID, true><<<GEMM_BLOCKS, 256>>>(nullptr, ws1, 0);
    edge_kernel<<<EDGE_BLOCKS, 256>>>(ei);
    gemm2_kernel<<<GEMM_BLOCKS, 256>>>(bs1, ws2, bs2, 1);
    bn_finalize_kernel<<<1, 64>>>(gms, bts, 1);

    // ---- layer 2 (64 -> 64), applies layer-1 BN on load ----
    gemm1_kernel<HID, true><<<GEMM_BLOCKS, 256>>>(nullptr, ws1 + HID * HID, 1);
    edge_kernel<<<EDGE_BLOCKS, 256>>>(ei);
    gemm2_kernel<<<GEMM_BLOCKS, 256>>>(bs1 + HID, ws2 + HID * HID, bs2 + HID, 2);
    bn_finalize_kernel<<<1, 64>>>(gms + HID, bts + HID, 2);

    // ---- pool (applies layer-2 BN) + head ----
    pool_kernel<<<POOL_BLOCKS, 256>>>(batch);
    head_kernel<<<N_GRAPHS / 4, 128>>>(lin1w, lin1b, lin2w, lin2b, out);
}

// round 4
// speedup vs baseline: 2.8025x; 2.8025x over previous
#include <cuda_runtime.h>
#include <math.h>

#define N_NODES  50000
#define N_EDGES  800000
#define N_GRAPHS 1000
#define F_INPUT  128
#define HID      64
#define OUT_F    16
#define BN_EPS   1e-5f

// ---------------- scratch (static device globals; no allocation) ------------
__device__ float g_B0[N_NODES * HID];      // v / h_prev buffer
__device__ float g_B1[N_NODES * HID];      // t (transformed features)
__device__ float g_B2[N_NODES * HID];      // aggregation accumulator
__device__ float g_stats[3 * 2 * HID];     // per-layer sum, sumsq
__device__ float g_scale[3 * HID];         // folded BN scale
__device__ float g_shift[3 * HID];         // folded BN shift
__device__ float g_pooled[N_GRAPHS * HID]; // segment max

// ---------------- helpers ---------------------------------------------------
__device__ __forceinline__ void atomicMaxF(float* addr, float val) {
    if (val >= 0.f) atomicMax((int*)addr, __float_as_int(val));
    else            atomicMin((unsigned int*)addr, __float_as_uint(val));
}

__device__ __forceinline__ void red_add_v4(float* addr, float4 v) {
    asm volatile("red.global.add.v4.f32 [%0], {%1,%2,%3,%4};"
                 :: "l"(addr), "f"(v.x), "f"(v.y), "f"(v.z), "f"(v.w)
                 : "memory");
}

// ---------------- init: zero BN stats, pooled = -inf ------------------------
__global__ void init_kernel() {
    int i = blockIdx.x * blockDim.x + threadIdx.x;
    if (i < 3 * 2 * HID) g_stats[i] = 0.f;
    if (i < N_GRAPHS * HID) g_pooled[i] = -INFINITY;
}

// ---------------- gemm1: t = (affine(h)) @ w1 -> B1 and B2 ------------------
// 64-row tiles, 4x4 register blocking per thread; dynamic smem:
// [0, IN_F*HID)            weights
// [IN_F*HID, +64*IN_F)     activations
template <int IN_F, bool AFF>
__global__ void __launch_bounds__(256) gemm1_kernel(
    const float* __restrict__ h_in, const float* __restrict__ w, int prev_layer)
{
    extern __shared__ float smem[];
    float* w_sh = smem;                       // [IN_F][HID]
    float* h_sh = smem + IN_F * HID;          // [64][IN_F]
    int tid = threadIdx.x;

    for (int i = tid; i < IN_F * HID / 4; i += 256)
        ((float4*)w_sh)[i] = ((const float4*)w)[i];

    const float* h = AFF ? g_B0 : h_in;
    const float* scale = g_scale + prev_layer * HID;
    const float* shift = g_shift + prev_layer * HID;

    int rowbase = blockIdx.x * 64;
    int nrows = N_NODES - rowbase; if (nrows > 64) nrows = 64;
    const float4* hbase = (const float4*)(h + (long)rowbase * IN_F);
    for (int i = tid; i < 64 * IN_F / 4; i += 256) {
        int r = i / (IN_F / 4);
        float4 v = make_float4(0.f, 0.f, 0.f, 0.f);
        if (r < nrows) {
            v = hbase[i];
            if (AFF) {
                int k = (i % (IN_F / 4)) * 4;
                v.x = v.x * scale[k + 0] + shift[k + 0];
                v.y = v.y * scale[k + 1] + shift[k + 1];
                v.z = v.z * scale[k + 2] + shift[k + 2];
                v.w = v.w * scale[k + 3] + shift[k + 3];
            }
        }
        ((float4*)h_sh)[i] = v;
    }
    __syncthreads();

    int rg = tid >> 4, cg = tid & 15;
    int r0 = rg * 4, c0 = cg * 4;
    float acc[4][4];
#pragma unroll
    for (int r = 0; r < 4; r++)
#pragma unroll
        for (int j = 0; j < 4; j++) acc[r][j] = 0.f;

#pragma unroll 2
    for (int k = 0; k < IN_F; k += 4) {
        float hv[4][4];
#pragma unroll
        for (int r = 0; r < 4; r++)
            *(float4*)hv[r] = *(const float4*)&h_sh[(r0 + r) * IN_F + k];
#pragma unroll
        for (int kk = 0; kk < 4; kk++) {
            float4 wv = *(const float4*)&w_sh[(k + kk) * HID + c0];
#pragma unroll
            for (int r = 0; r < 4; r++) {
                acc[r][0] += hv[r][kk] * wv.x;
                acc[r][1] += hv[r][kk] * wv.y;
                acc[r][2] += hv[r][kk] * wv.z;
                acc[r][3] += hv[r][kk] * wv.w;
            }
        }
    }

#pragma unroll
    for (int r = 0; r < 4; r++) {
        if (r0 + r < nrows) {
            long off = (long)(rowbase + r0 + r) * HID + c0;
            float4 o = make_float4(acc[r][0], acc[r][1], acc[r][2], acc[r][3]);
            *(float4*)&g_B1[off] = o;
            *(float4*)&g_B2[off] = o;   // self term (eps=0 GIN)
        }
    }
}

// ---------------- edge scatter: B2[dst] += B1[src], v4 red ------------------
__global__ void __launch_bounds__(256) edge_kernel(const int* __restrict__ ei)
{
    int idx = blockIdx.x * blockDim.x + threadIdx.x; // N_EDGES*4 threads
    int e = idx >> 2;
    if (e >= N_EDGES) return;
    int c = (idx & 3) * 16;
    int s = __ldg(&ei[e]);
    int d = __ldg(&ei[N_EDGES + e]);
    const float4* tp = (const float4*)(g_B1 + (long)s * HID + c);
    float4 v0 = __ldg(tp + 0);
    float4 v1 = __ldg(tp + 1);
    float4 v2 = __ldg(tp + 2);
    float4 v3 = __ldg(tp + 3);
    float* ap = g_B2 + (long)d * HID + c;
    red_add_v4(ap + 0,  v0);
    red_add_v4(ap + 4,  v1);
    red_add_v4(ap + 8,  v2);
    red_add_v4(ap + 12, v3);
}

// ---------------- gemm2: u=relu(B2+b1); v=relu(u@w2+b2) -> B0; stats --------
__global__ void __launch_bounds__(256) gemm2_kernel(
    const float* __restrict__ b1, const float* __restrict__ w2,
    const float* __restrict__ b2, int layer)
{
    __shared__ float w_sh[HID * HID];
    __shared__ float u_sh[64 * HID];
    __shared__ float s_sum[HID];
    __shared__ float s_sq[HID];
    int tid = threadIdx.x;

    for (int i = tid; i < HID * HID / 4; i += 256)
        ((float4*)w_sh)[i] = ((const float4*)w2)[i];
    if (tid < HID) { s_sum[tid] = 0.f; s_sq[tid] = 0.f; }

    int rowbase = blockIdx.x * 64;
    int nrows = N_NODES - rowbase; if (nrows > 64) nrows = 64;
    const float4* abase = (const float4*)(g_B2 + (long)rowbase * HID);
    for (int i = tid; i < 64 * HID / 4; i += 256) {
        int r = i / (HID / 4);
        float4 v = make_float4(0.f, 0.f, 0.f, 0.f);
        if (r < nrows) {
            v = abase[i];
            int k = (i % (HID / 4)) * 4;
            v.x = fmaxf(v.x + b1[k + 0], 0.f);
            v.y = fmaxf(v.y + b1[k + 1], 0.f);
            v.z = fmaxf(v.z + b1[k + 2], 0.f);
            v.w = fmaxf(v.w + b1[k + 3], 0.f);
        }
        ((float4*)u_sh)[i] = v;
    }
    __syncthreads();

    int rg = tid >> 4, cg = tid & 15;
    int r0 = rg * 4, c0 = cg * 4;
    float acc[4][4];
#pragma unroll
    for (int r = 0; r < 4; r++)
#pragma unroll
        for (int j = 0; j < 4; j++) acc[r][j] = 0.f;

#pragma unroll 2
    for (int k = 0; k < HID; k += 4) {
        float uv[4][4];
#pragma unroll
        for (int r = 0; r < 4; r++)
            *(float4*)uv[r] = *(const float4*)&u_sh[(r0 + r) * HID + k];
#pragma unroll
        for (int kk = 0; kk < 4; kk++) {
            float4 wv = *(const float4*)&w_sh[(k + kk) * HID + c0];
#pragma unroll
            for (int r = 0; r < 4; r++) {
                acc[r][0] += uv[r][kk] * wv.x;
                acc[r][1] += uv[r][kk] * wv.y;
                acc[r][2] += uv[r][kk] * wv.z;
                acc[r][3] += uv[r][kk] * wv.w;
            }
        }
    }

    float4 bias = *(const float4*)&b2[c0];
    float ls[4] = {0.f, 0.f, 0.f, 0.f};
    float lq[4] = {0.f, 0.f, 0.f, 0.f};
#pragma unroll
    for (int r = 0; r < 4; r++) {
        if (r0 + r < nrows) {
            float4 o;
            o.x = fmaxf(acc[r][0] + bias.x, 0.f);
            o.y = fmaxf(acc[r][1] + bias.y, 0.f);
            o.z = fmaxf(acc[r][2] + bias.z, 0.f);
            o.w = fmaxf(acc[r][3] + bias.w, 0.f);
            *(float4*)&g_B0[(long)(rowbase + r0 + r) * HID + c0] = o;
            ls[0] += o.x; lq[0] += o.x * o.x;
            ls[1] += o.y; lq[1] += o.y * o.y;
            ls[2] += o.z; lq[2] += o.z * o.z;
            ls[3] += o.w; lq[3] += o.w * o.w;
        }
    }
#pragma unroll
    for (int j = 0; j < 4; j++) {
        atomicAdd(&s_sum[c0 + j], ls[j]);
        atomicAdd(&s_sq[c0 + j],  lq[j]);
    }
    __syncthreads();
    float* stats = g_stats + layer * 2 * HID;
    if (tid < HID) {
        atomicAdd(&stats[tid], s_sum[tid]);
        atomicAdd(&stats[HID + tid], s_sq[tid]);
    }
}

// ---------------- BN finalize: fold into scale/shift ------------------------
__global__ void bn_finalize_kernel(const float* __restrict__ gamma,
                                   const float* __restrict__ beta, int layer)
{
    int c = threadIdx.x;
    if (c >= HID) return;
    const float* stats = g_stats + layer * 2 * HID;
    float inv_n = 1.f / (float)N_NODES;
    float mu  = stats[c] * inv_n;
    float var = stats[HID + c] * inv_n - mu * mu;
    float s = gamma[c] * rsqrtf(var + BN_EPS);
    g_scale[layer * HID + c] = s;
    g_shift[layer * HID + c] = beta[c] - mu * s;
}

// ---------------- pool: segment max of affine(B0) ---------------------------
__global__ void __launch_bounds__(256) pool_kernel(const int* __restrict__ batch)
{
    int idx = blockIdx.x * blockDim.x + threadIdx.x; // N_NODES*32
    int node = idx >> 5;
    if (node >= N_NODES) return;
    int lane = idx & 31;
    int g = __ldg(&batch[node]);
    const float* scale = g_scale + 2 * HID;
    const float* shift = g_shift + 2 * HID;
    float p0 = g_B0[(long)node * HID + lane]      * scale[lane]      + shift[lane];
    float p1 = g_B0[(long)node * HID + lane + 32] * scale[lane + 32] + shift[lane + 32];
    atomicMaxF(&g_pooled[g * HID + lane], p0);
    atomicMaxF(&g_pooled[g * HID + lane + 32], p1);
}

// ---------------- head: relu(pooled@lin1+b1)@lin2+b2 ------------------------
__global__ void __launch_bounds__(128) head_kernel(
    const float* __restrict__ lin1_w, const float* __restrict__ lin1_b,
    const float* __restrict__ lin2_w, const float* __restrict__ lin2_b,
    float* __restrict__ out)
{
    __shared__ float w1_sh[HID * HID];
    __shared__ float w2_sh[HID * OUT_F];
    __shared__ float p_sh[4][HID];
    __shared__ float h_sh[4][HID];
    int tid = threadIdx.x, warp = tid >> 5, lane = tid & 31;

    for (int i = tid; i < HID * HID / 4; i += 128)
        ((float4*)w1_sh)[i] = ((const float4*)lin1_w)[i];
    for (int i = tid; i < HID * OUT_F / 4; i += 128)
        ((float4*)w2_sh)[i] = ((const float4*)lin2_w)[i];

    int g = blockIdx.x * 4 + warp;
    float p0 = g_pooled[g * HID + lane];
    float p1 = g_pooled[g * HID + lane + 32];
    if (!isfinite(p0)) p0 = 0.f;
    if (!isfinite(p1)) p1 = 0.f;
    p_sh[warp][lane] = p0;
    p_sh[warp][lane + 32] = p1;
    __syncthreads();

    float acc0 = lin1_b[lane], acc1 = lin1_b[lane + 32];
#pragma unroll 8
    for (int k = 0; k < HID; k++) {
        float pv = p_sh[warp][k];
        acc0 += pv * w1_sh[k * HID + lane];
        acc1 += pv * w1_sh[k * HID + lane + 32];
    }
    h_sh[warp][lane]      = fmaxf(acc0, 0.f);
    h_sh[warp][lane + 32] = fmaxf(acc1, 0.f);
    __syncwarp();

    if (lane < OUT_F) {
        float acc = lin2_b[lane];
#pragma unroll 8
        for (int k = 0; k < HID; k++)
            acc += h_sh[warp][k] * w2_sh[k * OUT_F + lane];
        out[g * OUT_F + lane] = acc;
    }
}

// ---------------- launch ----------------------------------------------------
extern "C" void kernel_launch(void* const* d_in, const int* in_sizes, int n_in,
                              void* d_out, int out_size)
{
    const float* x     = (const float*)d_in[0];
    const int*   ei    = (const int*)d_in[1];    // int32 (JAX x64 disabled)
    const int*   batch = (const int*)d_in[2];
    const float* l0_w1 = (const float*)d_in[3];
    const float* l0_b1 = (const float*)d_in[4];
    const float* l0_w2 = (const float*)d_in[5];
    const float* l0_b2 = (const float*)d_in[6];
    const float* l0_g  = (const float*)d_in[7];
    const float* l0_be = (const float*)d_in[8];
    const float* ws1   = (const float*)d_in[9];
    const float* bs1   = (const float*)d_in[10];
    const float* ws2   = (const float*)d_in[11];
    const float* bs2   = (const float*)d_in[12];
    const float* gms   = (const float*)d_in[13];
    const float* bts   = (const float*)d_in[14];
    const float* lin1w = (const float*)d_in[15];
    const float* lin1b = (const float*)d_in[16];
    const float* lin2w = (const float*)d_in[17];
    const float* lin2b = (const float*)d_in[18];
    float* out = (float*)d_out;

    const int GEMM_BLOCKS = (N_NODES + 63) / 64;       // 782
    const int EDGE_BLOCKS = (N_EDGES * 4) / 256;       // 12500
    const int POOL_BLOCKS = (N_NODES * 32) / 256;      // 6250

    const int SMEM_G1_L0 = (F_INPUT * HID + 64 * F_INPUT) * 4;  // 64 KB
    const int SMEM_G1_LN = (HID * HID + 64 * HID) * 4;          // 32 KB
    cudaFuncSetAttribute(gemm1_kernel<F_INPUT, false>,
                         cudaFuncAttributeMaxDynamicSharedMemorySize, SMEM_G1_L0);
    cudaFuncSetAttribute(gemm1_kernel<HID, true>,
                         cudaFuncAttributeMaxDynamicSharedMemorySize, SMEM_G1_LN);

    init_kernel<<<(N_GRAPHS * HID + 255) / 256, 256>>>();

    // ---- layer 0 (128 -> 64), no input affine ----
    gemm1_kernel<F_INPUT, false><<<GEMM_BLOCKS, 256, SMEM_G1_L0>>>(x, l0_w1, 0);
    edge_kernel<<<EDGE_BLOCKS, 256>>>(ei);
    gemm2_kernel<<<GEMM_BLOCKS, 256>>>(l0_b1, l0_w2, l0_b2, 0);
    bn_finalize_kernel<<<1, 64>>>(l0_g, l0_be, 0);

    // ---- layer 1 (64 -> 64), applies layer-0 BN on load ----
    gemm1_kernel<HID, true><<<GEMM_BLOCKS, 256, SMEM_G1_LN>>>(nullptr, ws1, 0);
    edge_kernel<<<EDGE_BLOCKS, 256>>>(ei);
    gemm2_kernel<<<GEMM_BLOCKS, 256>>>(bs1, ws2, bs2, 1);
    bn_finalize_kernel<<<1, 64>>>(gms, bts, 1);

    // ---- layer 2 (64 -> 64), applies layer-1 BN on load ----
    gemm1_kernel<HID, true><<<GEMM_BLOCKS, 256, SMEM_G1_LN>>>(nullptr, ws1 + HID * HID, 1);
    edge_kernel<<<EDGE_BLOCKS, 256>>>(ei);
    gemm2_kernel<<<GEMM_BLOCKS, 256>>>(bs1 + HID, ws2 + HID * HID, bs2 + HID, 2);
    bn_finalize_kernel<<<1, 64>>>(gms + HID, bts + HID, 2);

    // ---- pool (applies layer-2 BN) + head ----
    pool_kernel<<<POOL_BLOCKS, 256>>>(batch);
    head_kernel<<<N_GRAPHS / 4, 128>>>(lin1w, lin1b, lin2w, lin2b, out);
}

// round 5
// speedup vs baseline: 3.4457x; 1.2295x over previous
#include <cuda_runtime.h>
#include <math.h>

#define N_NODES  50000
#define N_EDGES  800000
#define N_GRAPHS 1000
#define F_INPUT  128
#define HID      64
#define OUT_F    16
#define BN_EPS   1e-5f
#define NBLK256  ((N_NODES + 255) / 256)   // 196

// ---------------- scratch (static device globals; no allocation) ------------
__device__ float g_B0[N_NODES * HID];      // v (post MLP, pre-BN)
__device__ float g_B1[N_NODES * HID];      // t (transformed features)
__device__ float g_B2[N_NODES * HID];      // aggregation result
__device__ float g_stats[3 * 2 * HID];     // per-layer sum, sumsq
__device__ float g_scale[3 * HID];         // BN scale (pool uses layer 2)
__device__ float g_shift[3 * HID];
__device__ float g_w1f[2 * HID * HID];     // BN-folded next-layer weights
__device__ float g_b1f[2 * HID];           // BN-folded row bias
__device__ float g_pooled[N_GRAPHS * HID]; // segment max
// CSR scratch
__device__ int g_deg[N_NODES];
__device__ int g_off[N_NODES + 1];
__device__ int g_cur[N_NODES];
__device__ int g_csr[N_EDGES];
__device__ int g_bsum[NBLK256];
__device__ int g_boff[NBLK256];

// ---------------- helpers ---------------------------------------------------
__device__ __forceinline__ void atomicMaxF(float* addr, float val) {
    if (val >= 0.f) atomicMax((int*)addr, __float_as_int(val));
    else            atomicMin((unsigned int*)addr, __float_as_uint(val));
}
__device__ __forceinline__ void add4(float4& a, const float4 b) {
    a.x += b.x; a.y += b.y; a.z += b.z; a.w += b.w;
}

// ---------------- init: zero deg + stats, pooled = -inf ---------------------
__global__ void init_kernel() {
    int i = blockIdx.x * blockDim.x + threadIdx.x;
    if (i < N_GRAPHS * HID) g_pooled[i] = -INFINITY;
    if (i < N_NODES) g_deg[i] = 0;
    if (i < 3 * 2 * HID) g_stats[i] = 0.f;
}

// ---------------- CSR build -------------------------------------------------
__global__ void hist_kernel(const int* __restrict__ ei) {
    int e = blockIdx.x * blockDim.x + threadIdx.x;
    if (e < N_EDGES) atomicAdd(&g_deg[__ldg(&ei[N_EDGES + e])], 1);
}
__global__ void scanA_kernel() {   // per-block degree sums
    __shared__ int sh[256];
    int tid = threadIdx.x;
    int n = blockIdx.x * 256 + tid;
    sh[tid] = (n < N_NODES) ? g_deg[n] : 0;
    __syncthreads();
    for (int s = 128; s > 0; s >>= 1) {
        if (tid < s) sh[tid] += sh[tid + s];
        __syncthreads();
    }
    if (tid == 0) g_bsum[blockIdx.x] = sh[0];
}
__global__ void scanB_kernel() {   // scan of block sums (1 block, 256 thr)
    __shared__ int sh[256];
    int tid = threadIdx.x;
    int v = (tid < NBLK256) ? g_bsum[tid] : 0;
    sh[tid] = v;
    __syncthreads();
    for (int d = 1; d < 256; d <<= 1) {
        int t = (tid >= d) ? sh[tid - d] : 0;
        __syncthreads();
        sh[tid] += t;
        __syncthreads();
    }
    if (tid < NBLK256) g_boff[tid] = sh[tid] - v;   // exclusive
    if (tid == 255) g_off[N_NODES] = sh[255];
}
__global__ void scanC_kernel() {   // per-node offsets
    __shared__ int sh[256];
    int tid = threadIdx.x;
    int n = blockIdx.x * 256 + tid;
    int v = (n < N_NODES) ? g_deg[n] : 0;
    sh[tid] = v;
    __syncthreads();
    for (int d = 1; d < 256; d <<= 1) {
        int t = (tid >= d) ? sh[tid - d] : 0;
        __syncthreads();
        sh[tid] += t;
        __syncthreads();
    }
    if (n < N_NODES) {
        int off = g_boff[blockIdx.x] + sh[tid] - v;
        g_off[n] = off;
        g_cur[n] = off;
    }
}
__global__ void fill_kernel(const int* __restrict__ ei) {
    int e = blockIdx.x * blockDim.x + threadIdx.x;
    if (e >= N_EDGES) return;
    int s = __ldg(&ei[e]);
    int d = __ldg(&ei[N_EDGES + e]);
    int pos = atomicAdd(&g_cur[d], 1);
    g_csr[pos] = s;
}

// ---------------- gemm1: t = in @ W (+bias) -> B1 ---------------------------
// 128-row tile, 128 threads, 8x8 register blocking.
template <int IN_F, bool FOLDED>
__global__ void __launch_bounds__(128) gemm1_kernel(
    const float* __restrict__ h_in, const float* __restrict__ w_in, int fidx)
{
    extern __shared__ float smem[];
    float* w_sh = smem;                 // [IN_F][HID]
    float* h_sh = smem + IN_F * HID;    // [128][IN_F]
    int tid = threadIdx.x;

    const float* w = FOLDED ? (g_w1f + fidx * HID * HID) : w_in;
    const float* h = FOLDED ? g_B0 : h_in;

    for (int i = tid; i < IN_F * HID / 4; i += 128)
        ((float4*)w_sh)[i] = ((const float4*)w)[i];

    int rowbase = blockIdx.x * 128;
    int nrows = N_NODES - rowbase; if (nrows > 128) nrows = 128;
    const float4* hbase = (const float4*)(h + (long)rowbase * IN_F);
    for (int i = tid; i < 128 * IN_F / 4; i += 128) {
        int r = i / (IN_F / 4);
        ((float4*)h_sh)[i] = (r < nrows) ? hbase[i] : make_float4(0.f, 0.f, 0.f, 0.f);
    }
    __syncthreads();

    int rg = tid >> 3, cg = tid & 7;
    int r0 = rg * 8, c0 = cg * 8;
    float acc[8][8];
#pragma unroll
    for (int r = 0; r < 8; r++)
#pragma unroll
        for (int j = 0; j < 8; j++) acc[r][j] = 0.f;

    for (int k = 0; k < IN_F; k += 4) {
        float4 av[8];
#pragma unroll
        for (int r = 0; r < 8; r++)
            av[r] = *(const float4*)&h_sh[(r0 + r) * IN_F + k];
#pragma unroll
        for (int kk = 0; kk < 4; kk++) {
            float4 w0 = *(const float4*)&w_sh[(k + kk) * HID + c0];
            float4 w1 = *(const float4*)&w_sh[(k + kk) * HID + c0 + 4];
#pragma unroll
            for (int r = 0; r < 8; r++) {
                float a = (kk == 0) ? av[r].x : (kk == 1) ? av[r].y
                         : (kk == 2) ? av[r].z : av[r].w;
                acc[r][0] += a * w0.x; acc[r][1] += a * w0.y;
                acc[r][2] += a * w0.z; acc[r][3] += a * w0.w;
                acc[r][4] += a * w1.x; acc[r][5] += a * w1.y;
                acc[r][6] += a * w1.z; acc[r][7] += a * w1.w;
            }
        }
    }

    float4 b0 = make_float4(0.f, 0.f, 0.f, 0.f), b1 = b0;
    if (FOLDED) {
        b0 = *(const float4*)&g_b1f[fidx * HID + c0];
        b1 = *(const float4*)&g_b1f[fidx * HID + c0 + 4];
    }
#pragma unroll
    for (int r = 0; r < 8; r++) {
        if (r0 + r < nrows) {
            long off = (long)(rowbase + r0 + r) * HID + c0;
            *(float4*)&g_B1[off] = make_float4(acc[r][0] + b0.x, acc[r][1] + b0.y,
                                               acc[r][2] + b0.z, acc[r][3] + b0.w);
            *(float4*)&g_B1[off + 4] = make_float4(acc[r][4] + b1.x, acc[r][5] + b1.y,
                                                   acc[r][6] + b1.z, acc[r][7] + b1.w);
        }
    }
}

// ---------------- aggregate (CSR gather): B2[n] = B1[n] + sum B1[src] -------
__global__ void __launch_bounds__(256) agg_kernel()
{
    int gidx = blockIdx.x * blockDim.x + threadIdx.x; // 8 threads per node
    int node = gidx >> 3;
    if (node >= N_NODES) return;
    int c = (gidx & 7) * 8;
    long base = (long)node * HID + c;
    float4 a0 = *(const float4*)&g_B1[base];
    float4 a1 = *(const float4*)&g_B1[base + 4];
    int p = g_off[node], end = g_off[node + 1];
    for (; p + 2 <= end; p += 2) {
        int s0 = __ldg(&g_csr[p]);
        int s1 = __ldg(&g_csr[p + 1]);
        const float4* t0 = (const float4*)(g_B1 + (long)s0 * HID + c);
        const float4* t1 = (const float4*)(g_B1 + (long)s1 * HID + c);
        float4 v00 = __ldg(t0), v01 = __ldg(t0 + 1);
        float4 v10 = __ldg(t1), v11 = __ldg(t1 + 1);
        add4(a0, v00); add4(a1, v01);
        add4(a0, v10); add4(a1, v11);
    }
    if (p < end) {
        int s0 = __ldg(&g_csr[p]);
        const float4* t0 = (const float4*)(g_B1 + (long)s0 * HID + c);
        add4(a0, __ldg(t0)); add4(a1, __ldg(t0 + 1));
    }
    *(float4*)&g_B2[base] = a0;
    *(float4*)&g_B2[base + 4] = a1;
}

// ---------------- gemm2: u=relu(B2+b1); v=relu(u@w2+b2) -> B0; stats --------
__global__ void __launch_bounds__(128) gemm2_kernel(
    const float* __restrict__ b1, const float* __restrict__ w2,
    const float* __restrict__ b2, int layer)
{
    extern __shared__ float smem[];
    float* w_sh = smem;                 // [HID][HID]
    float* u_sh = smem + HID * HID;     // [128][HID]
    __shared__ float s_sum[HID];
    __shared__ float s_sq[HID];
    int tid = threadIdx.x;

    for (int i = tid; i < HID * HID / 4; i += 128)
        ((float4*)w_sh)[i] = ((const float4*)w2)[i];
    if (tid < HID) { s_sum[tid] = 0.f; s_sq[tid] = 0.f; }

    int rowbase = blockIdx.x * 128;
    int nrows = N_NODES - rowbase; if (nrows > 128) nrows = 128;
    const float4* abase = (const float4*)(g_B2 + (long)rowbase * HID);
    for (int i = tid; i < 128 * HID / 4; i += 128) {
        int r = i >> 4;                 // /(HID/4)
        float4 v = make_float4(0.f, 0.f, 0.f, 0.f);
        if (r < nrows) {
            v = abase[i];
            int k = (i & 15) * 4;
            v.x = fmaxf(v.x + b1[k + 0], 0.f);
            v.y = fmaxf(v.y + b1[k + 1], 0.f);
            v.z = fmaxf(v.z + b1[k + 2], 0.f);
            v.w = fmaxf(v.w + b1[k + 3], 0.f);
        }
        ((float4*)u_sh)[i] = v;
    }
    __syncthreads();

    int rg = tid >> 3, cg = tid & 7;
    int r0 = rg * 8, c0 = cg * 8;
    float acc[8][8];
#pragma unroll
    for (int r = 0; r < 8; r++)
#pragma unroll
        for (int j = 0; j < 8; j++) acc[r][j] = 0.f;

    for (int k = 0; k < HID; k += 4) {
        float4 av[8];
#pragma unroll
        for (int r = 0; r < 8; r++)
            av[r] = *(const float4*)&u_sh[(r0 + r) * HID + k];
#pragma unroll
        for (int kk = 0; kk < 4; kk++) {
            float4 w0 = *(const float4*)&w_sh[(k + kk) * HID + c0];
            float4 w1 = *(const float4*)&w_sh[(k + kk) * HID + c0 + 4];
#pragma unroll
            for (int r = 0; r < 8; r++) {
                float a = (kk == 0) ? av[r].x : (kk == 1) ? av[r].y
                         : (kk == 2) ? av[r].z : av[r].w;
                acc[r][0] += a * w0.x; acc[r][1] += a * w0.y;
                acc[r][2] += a * w0.z; acc[r][3] += a * w0.w;
                acc[r][4] += a * w1.x; acc[r][5] += a * w1.y;
                acc[r][6] += a * w1.z; acc[r][7] += a * w1.w;
            }
        }
    }

    float4 bb0 = *(const float4*)&b2[c0];
    float4 bb1 = *(const float4*)&b2[c0 + 4];
    float ls[8] = {0,0,0,0,0,0,0,0};
    float lq[8] = {0,0,0,0,0,0,0,0};
#pragma unroll
    for (int r = 0; r < 8; r++) {
        if (r0 + r < nrows) {
            float o[8];
            o[0] = fmaxf(acc[r][0] + bb0.x, 0.f); o[1] = fmaxf(acc[r][1] + bb0.y, 0.f);
            o[2] = fmaxf(acc[r][2] + bb0.z, 0.f); o[3] = fmaxf(acc[r][3] + bb0.w, 0.f);
            o[4] = fmaxf(acc[r][4] + bb1.x, 0.f); o[5] = fmaxf(acc[r][5] + bb1.y, 0.f);
            o[6] = fmaxf(acc[r][6] + bb1.z, 0.f); o[7] = fmaxf(acc[r][7] + bb1.w, 0.f);
            long off = (long)(rowbase + r0 + r) * HID + c0;
            *(float4*)&g_B0[off]     = make_float4(o[0], o[1], o[2], o[3]);
            *(float4*)&g_B0[off + 4] = make_float4(o[4], o[5], o[6], o[7]);
#pragma unroll
            for (int j = 0; j < 8; j++) { ls[j] += o[j]; lq[j] += o[j] * o[j]; }
        }
    }
#pragma unroll
    for (int j = 0; j < 8; j++) {
        atomicAdd(&s_sum[c0 + j], ls[j]);
        atomicAdd(&s_sq[c0 + j],  lq[j]);
    }
    __syncthreads();
    float* stats = g_stats + layer * 2 * HID;
    if (tid < HID) {
        atomicAdd(&stats[tid], s_sum[tid]);
        atomicAdd(&stats[HID + tid], s_sq[tid]);
    }
}

// ---------------- BN finalize + fold into next layer's weights --------------
__global__ void bn_fold_kernel(const float* __restrict__ gamma,
                               const float* __restrict__ beta,
                               const float* __restrict__ w1_next,
                               int layer, int fidx, int do_fold)
{
    __shared__ float sc[HID], sf[HID];
    int tid = threadIdx.x; // 256
    if (tid < HID) {
        const float* stats = g_stats + layer * 2 * HID;
        float inv_n = 1.f / (float)N_NODES;
        float mu  = stats[tid] * inv_n;
        float var = stats[HID + tid] * inv_n - mu * mu;
        float s = gamma[tid] * rsqrtf(var + BN_EPS);
        sc[tid] = s;
        sf[tid] = beta[tid] - mu * s;
        g_scale[layer * HID + tid] = s;
        g_shift[layer * HID + tid] = sf[tid];
    }
    __syncthreads();
    if (do_fold) {
        for (int i = tid; i < HID * HID; i += 256)
            g_w1f[fidx * HID * HID + i] = sc[i >> 6] * w1_next[i];
        if (tid < HID) {
            float b = 0.f;
            for (int k = 0; k < HID; k++)
                b += sf[k] * w1_next[k * HID + tid];
            g_b1f[fidx * HID + tid] = b;
        }
    }
}

// ---------------- pool: segment max of affine(B0) ---------------------------
__global__ void __launch_bounds__(256) pool_kernel(const int* __restrict__ batch)
{
    int idx = blockIdx.x * blockDim.x + threadIdx.x; // N_NODES*32
    int node = idx >> 5;
    if (node >= N_NODES) return;
    int lane = idx & 31;
    int g = __ldg(&batch[node]);
    const float* scale = g_scale + 2 * HID;
    const float* shift = g_shift + 2 * HID;
    float p0 = g_B0[(long)node * HID + lane]      * scale[lane]      + shift[lane];
    float p1 = g_B0[(long)node * HID + lane + 32] * scale[lane + 32] + shift[lane + 32];
    atomicMaxF(&g_pooled[g * HID + lane], p0);
    atomicMaxF(&g_pooled[g * HID + lane + 32], p1);
}

// ---------------- head: relu(pooled@lin1+b1)@lin2+b2 ------------------------
__global__ void __launch_bounds__(128) head_kernel(
    const float* __restrict__ lin1_w, const float* __restrict__ lin1_b,
    const float* __restrict__ lin2_w, const float* __restrict__ lin2_b,
    float* __restrict__ out)
{
    __shared__ float w1_sh[HID * HID];
    __shared__ float w2_sh[HID * OUT_F];
    __shared__ float p_sh[4][HID];
    __shared__ float h_sh[4][HID];
    int tid = threadIdx.x, warp = tid >> 5, lane = tid & 31;

    for (int i = tid; i < HID * HID / 4; i += 128)
        ((float4*)w1_sh)[i] = ((const float4*)lin1_w)[i];
    for (int i = tid; i < HID * OUT_F / 4; i += 128)
        ((float4*)w2_sh)[i] = ((const float4*)lin2_w)[i];

    int g = blockIdx.x * 4 + warp;
    float p0 = g_pooled[g * HID + lane];
    float p1 = g_pooled[g * HID + lane + 32];
    if (!isfinite(p0)) p0 = 0.f;
    if (!isfinite(p1)) p1 = 0.f;
    p_sh[warp][lane] = p0;
    p_sh[warp][lane + 32] = p1;
    __syncthreads();

    float acc0 = lin1_b[lane], acc1 = lin1_b[lane + 32];
#pragma unroll 8
    for (int k = 0; k < HID; k++) {
        float pv = p_sh[warp][k];
        acc0 += pv * w1_sh[k * HID + lane];
        acc1 += pv * w1_sh[k * HID + lane + 32];
    }
    h_sh[warp][lane]      = fmaxf(acc0, 0.f);
    h_sh[warp][lane + 32] = fmaxf(acc1, 0.f);
    __syncwarp();

    if (lane < OUT_F) {
        float acc = lin2_b[lane];
#pragma unroll 8
        for (int k = 0; k < HID; k++)
            acc += h_sh[warp][k] * w2_sh[k * OUT_F + lane];
        out[g * OUT_F + lane] = acc;
    }
}

// ---------------- launch ----------------------------------------------------
extern "C" void kernel_launch(void* const* d_in, const int* in_sizes, int n_in,
                              void* d_out, int out_size)
{
    const float* x     = (const float*)d_in[0];
    const int*   ei    = (const int*)d_in[1];    // int32 (JAX x64 disabled)
    const int*   batch = (const int*)d_in[2];
    const float* l0_w1 = (const float*)d_in[3];
    const float* l0_b1 = (const float*)d_in[4];
    const float* l0_w2 = (const float*)d_in[5];
    const float* l0_b2 = (const float*)d_in[6];
    const float* l0_g  = (const float*)d_in[7];
    const float* l0_be = (const float*)d_in[8];
    const float* ws1   = (const float*)d_in[9];
    const float* bs1   = (const float*)d_in[10];
    const float* ws2   = (const float*)d_in[11];
    const float* bs2   = (const float*)d_in[12];
    const float* gms   = (const float*)d_in[13];
    const float* bts   = (const float*)d_in[14];
    const float* lin1w = (const float*)d_in[15];
    const float* lin1b = (const float*)d_in[16];
    const float* lin2w = (const float*)d_in[17];
    const float* lin2b = (const float*)d_in[18];
    float* out = (float*)d_out;

    const int GEMM_BLOCKS = (N_NODES + 127) / 128;     // 391
    const int AGG_BLOCKS  = (N_NODES * 8 + 255) / 256; // 1563
    const int POOL_BLOCKS = (N_NODES * 32) / 256;      // 6250
    const int EDGE_BLOCKS = (N_EDGES + 255) / 256;     // 3125

    const int SMEM_G1_L0 = (F_INPUT * HID + 128 * F_INPUT) * 4;  // 96 KB
    const int SMEM_G1_LN = (HID * HID + 128 * HID) * 4;          // 48 KB
    const int SMEM_G2    = (HID * HID + 128 * HID) * 4;          // 48 KB
    cudaFuncSetAttribute(gemm1_kernel<F_INPUT, false>,
                         cudaFuncAttributeMaxDynamicSharedMemorySize, SMEM_G1_L0);
    cudaFuncSetAttribute(gemm1_kernel<HID, true>,
                         cudaFuncAttributeMaxDynamicSharedMemorySize, SMEM_G1_LN);
    cudaFuncSetAttribute(gemm2_kernel,
                         cudaFuncAttributeMaxDynamicSharedMemorySize, SMEM_G2);

    // ---- init + CSR build (once; reused by all 3 layers) ----
    init_kernel<<<(N_GRAPHS * HID + 255) / 256, 256>>>();
    hist_kernel<<<EDGE_BLOCKS, 256>>>(ei);
    scanA_kernel<<<NBLK256, 256>>>();
    scanB_kernel<<<1, 256>>>();
    scanC_kernel<<<NBLK256, 256>>>();
    fill_kernel<<<EDGE_BLOCKS, 256>>>(ei);

    // ---- layer 0 (128 -> 64) ----
    gemm1_kernel<F_INPUT, false><<<GEMM_BLOCKS, 128, SMEM_G1_L0>>>(x, l0_w1, 0);
    agg_kernel<<<AGG_BLOCKS, 256>>>();
    gemm2_kernel<<<GEMM_BLOCKS, 128, SMEM_G2>>>(l0_b1, l0_w2, l0_b2, 0);
    bn_fold_kernel<<<1, 256>>>(l0_g, l0_be, ws1, 0, 0, 1);

    // ---- layer 1 (64 -> 64) via folded weights ----
    gemm1_kernel<HID, true><<<GEMM_BLOCKS, 128, SMEM_G1_LN>>>(nullptr, nullptr, 0);
    agg_kernel<<<AGG_BLOCKS, 256>>>();
    gemm2_kernel<<<GEMM_BLOCKS, 128, SMEM_G2>>>(bs1, ws2, bs2, 1);
    bn_fold_kernel<<<1, 256>>>(gms, bts, ws1 + HID * HID, 1, 1, 1);

    // ---- layer 2 (64 -> 64) via folded weights ----
    gemm1_kernel<HID, true><<<GEMM_BLOCKS, 128, SMEM_G1_LN>>>(nullptr, nullptr, 1);
    agg_kernel<<<AGG_BLOCKS, 256>>>();
    gemm2_kernel<<<GEMM_BLOCKS, 128, SMEM_G2>>>(bs1 + HID, ws2 + HID * HID, bs2 + HID, 2);
    bn_fold_kernel<<<1, 256>>>(gms + HID, bts + HID, nullptr, 2, 0, 0);

    // ---- pool (applies layer-2 BN) + head ----
    pool_kernel<<<POOL_BLOCKS, 256>>>(batch);
    head_kernel<<<N_GRAPHS / 4, 128>>>(lin1w, lin1b, lin2w, lin2b, out);
}

// round 6
// speedup vs baseline: 3.6653x; 1.0637x over previous
#include <cuda_runtime.h>
#include <math.h>

#define N_NODES  50000
#define N_EDGES  800000
#define N_GRAPHS 1000
#define F_INPUT  128
#define HID      64
#define OUT_F    16
#define BN_EPS   1e-5f
#define NBLK256  ((N_NODES + 255) / 256)   // 196

// ---------------- scratch (static device globals; no allocation) ------------
__device__ float g_B0[N_NODES * HID];      // v (post MLP, pre-BN)
__device__ float g_B1[N_NODES * HID];      // t (transformed features)
__device__ float g_stats[3 * 2 * HID];     // per-layer sum, sumsq
__device__ float g_pooled[N_GRAPHS * HID]; // segment max
// CSR scratch
__device__ int g_deg[N_NODES];
__device__ int g_off[N_NODES + 1];
__device__ int g_cur[N_NODES];
__device__ int g_csr[N_EDGES];
__device__ int g_bsum[NBLK256];
__device__ int g_boff[NBLK256];

// ---------------- helpers ---------------------------------------------------
__device__ __forceinline__ void atomicMaxF(float* addr, float val) {
    if (val >= 0.f) atomicMax((int*)addr, __float_as_int(val));
    else            atomicMin((unsigned int*)addr, __float_as_uint(val));
}
__device__ __forceinline__ void add4(float4& a, const float4 b) {
    a.x += b.x; a.y += b.y; a.z += b.z; a.w += b.w;
}

// ---------------- init ------------------------------------------------------
__global__ void init_kernel() {
    int i = blockIdx.x * blockDim.x + threadIdx.x;
    if (i < N_GRAPHS * HID) g_pooled[i] = -INFINITY;
    if (i < N_NODES) g_deg[i] = 0;
    if (i < 3 * 2 * HID) g_stats[i] = 0.f;
}

// ---------------- CSR build -------------------------------------------------
__global__ void hist_kernel(const int* __restrict__ ei) {
    int e = blockIdx.x * blockDim.x + threadIdx.x;
    if (e < N_EDGES) atomicAdd(&g_deg[__ldg(&ei[N_EDGES + e])], 1);
}
__global__ void scanA_kernel() {
    __shared__ int sh[256];
    int tid = threadIdx.x;
    int n = blockIdx.x * 256 + tid;
    sh[tid] = (n < N_NODES) ? g_deg[n] : 0;
    __syncthreads();
    for (int s = 128; s > 0; s >>= 1) {
        if (tid < s) sh[tid] += sh[tid + s];
        __syncthreads();
    }
    if (tid == 0) g_bsum[blockIdx.x] = sh[0];
}
__global__ void scanB_kernel() {
    __shared__ int sh[256];
    int tid = threadIdx.x;
    int v = (tid < NBLK256) ? g_bsum[tid] : 0;
    sh[tid] = v;
    __syncthreads();
    for (int d = 1; d < 256; d <<= 1) {
        int t = (tid >= d) ? sh[tid - d] : 0;
        __syncthreads();
        sh[tid] += t;
        __syncthreads();
    }
    if (tid < NBLK256) g_boff[tid] = sh[tid] - v;
    if (tid == 255) g_off[N_NODES] = sh[255];
}
__global__ void scanC_kernel() {
    __shared__ int sh[256];
    int tid = threadIdx.x;
    int n = blockIdx.x * 256 + tid;
    int v = (n < N_NODES) ? g_deg[n] : 0;
    sh[tid] = v;
    __syncthreads();
    for (int d = 1; d < 256; d <<= 1) {
        int t = (tid >= d) ? sh[tid - d] : 0;
        __syncthreads();
        sh[tid] += t;
        __syncthreads();
    }
    if (n < N_NODES) {
        int off = g_boff[blockIdx.x] + sh[tid] - v;
        g_off[n] = off;
        g_cur[n] = off;
    }
}
__global__ void fill_kernel(const int* __restrict__ ei) {
    int e = blockIdx.x * blockDim.x + threadIdx.x;
    if (e >= N_EDGES) return;
    int s = __ldg(&ei[e]);
    int d = __ldg(&ei[N_EDGES + e]);
    int pos = atomicAdd(&g_cur[d], 1);
    g_csr[pos] = s;
}

// ---------------- gemm1: t = (BN-affine(h)) @ W (+folded bias) -> B1 --------
// 128-row tile, 128 threads, 8x8 register blocking.
// FOLDED: computes BN scale/shift from g_stats[stats_layer] inline and folds
// into the weight load; bias = sum_k shift[k]*W[k][c].
template <int IN_F, bool FOLDED>
__global__ void __launch_bounds__(128) gemm1_kernel(
    const float* __restrict__ h_in, const float* __restrict__ w,
    const float* __restrict__ gamma, const float* __restrict__ beta,
    int stats_layer)
{
    extern __shared__ float smem[];
    float* w_sh = smem;                 // [IN_F][HID]
    float* h_sh = smem + IN_F * HID;    // [128][IN_F]
    __shared__ float sc[HID], sf[HID], bias_sh[HID];
    int tid = threadIdx.x;

    if (FOLDED) {
        if (tid < HID) {
            const float* stats = g_stats + stats_layer * 2 * HID;
            float inv_n = 1.f / (float)N_NODES;
            float mu  = stats[tid] * inv_n;
            float var = stats[HID + tid] * inv_n - mu * mu;
            float s = gamma[tid] * rsqrtf(var + BN_EPS);
            sc[tid] = s;
            sf[tid] = beta[tid] - mu * s;
        }
        __syncthreads();
    }

    const float* h = FOLDED ? g_B0 : h_in;
    for (int i = tid; i < IN_F * HID / 4; i += 128) {
        float4 v = ((const float4*)w)[i];
        if (FOLDED) {
            float s = sc[(i * 4) >> 6];   // k index (row of W)
            v.x *= s; v.y *= s; v.z *= s; v.w *= s;
        }
        ((float4*)w_sh)[i] = v;
    }

    int rowbase = blockIdx.x * 128;
    int nrows = N_NODES - rowbase; if (nrows > 128) nrows = 128;
    const float4* hbase = (const float4*)(h + (long)rowbase * IN_F);
    for (int i = tid; i < 128 * IN_F / 4; i += 128) {
        int r = i / (IN_F / 4);
        ((float4*)h_sh)[i] = (r < nrows) ? hbase[i] : make_float4(0.f, 0.f, 0.f, 0.f);
    }

    if (FOLDED && tid < HID) {
        float b = 0.f;
#pragma unroll 8
        for (int k = 0; k < HID; k++)
            b += sf[k] * __ldg(&w[k * HID + tid]);
        bias_sh[tid] = b;
    }
    __syncthreads();

    int rg = tid >> 3, cg = tid & 7;
    int r0 = rg * 8, c0 = cg * 8;
    float acc[8][8];
#pragma unroll
    for (int r = 0; r < 8; r++)
#pragma unroll
        for (int j = 0; j < 8; j++) acc[r][j] = 0.f;

    for (int k = 0; k < IN_F; k += 4) {
        float4 av[8];
#pragma unroll
        for (int r = 0; r < 8; r++)
            av[r] = *(const float4*)&h_sh[(r0 + r) * IN_F + k];
#pragma unroll
        for (int kk = 0; kk < 4; kk++) {
            float4 w0 = *(const float4*)&w_sh[(k + kk) * HID + c0];
            float4 w1 = *(const float4*)&w_sh[(k + kk) * HID + c0 + 4];
#pragma unroll
            for (int r = 0; r < 8; r++) {
                float a = (kk == 0) ? av[r].x : (kk == 1) ? av[r].y
                         : (kk == 2) ? av[r].z : av[r].w;
                acc[r][0] += a * w0.x; acc[r][1] += a * w0.y;
                acc[r][2] += a * w0.z; acc[r][3] += a * w0.w;
                acc[r][4] += a * w1.x; acc[r][5] += a * w1.y;
                acc[r][6] += a * w1.z; acc[r][7] += a * w1.w;
            }
        }
    }

    float4 b0 = make_float4(0.f, 0.f, 0.f, 0.f), b1v = b0;
    if (FOLDED) {
        b0  = *(const float4*)&bias_sh[c0];
        b1v = *(const float4*)&bias_sh[c0 + 4];
    }
#pragma unroll
    for (int r = 0; r < 8; r++) {
        if (r0 + r < nrows) {
            long off = (long)(rowbase + r0 + r) * HID + c0;
            *(float4*)&g_B1[off] = make_float4(acc[r][0] + b0.x, acc[r][1] + b0.y,
                                               acc[r][2] + b0.z, acc[r][3] + b0.w);
            *(float4*)&g_B1[off + 4] = make_float4(acc[r][4] + b1v.x, acc[r][5] + b1v.y,
                                                   acc[r][6] + b1v.z, acc[r][7] + b1v.w);
        }
    }
}

// ---------------- fused agg + gemm2 -----------------------------------------
// Phase 1: gather u[row] = relu(B1[row] + sum B1[csr] + b1) into smem.
// Phase 2: v = relu(u @ w2 + b2) -> B0; accumulate BN stats.
__global__ void __launch_bounds__(128) agg_gemm2_kernel(
    const float* __restrict__ b1, const float* __restrict__ w2,
    const float* __restrict__ b2, int layer)
{
    extern __shared__ float smem[];
    float* w_sh = smem;                 // [HID][HID]
    float* u_sh = smem + HID * HID;     // [128][HID]
    __shared__ float s_sum[HID];
    __shared__ float s_sq[HID];
    int tid = threadIdx.x;

    for (int i = tid; i < HID * HID / 4; i += 128)
        ((float4*)w_sh)[i] = ((const float4*)w2)[i];
    if (tid < HID) { s_sum[tid] = 0.f; s_sq[tid] = 0.f; }

    int rowbase = blockIdx.x * 128;
    int nrows = N_NODES - rowbase; if (nrows > 128) nrows = 128;

    // phase 1: gather (8 threads per row slice; 8 iterations cover 128 rows)
    for (int it = 0; it < 8; it++) {
        int task = it * 128 + tid;
        int row = task >> 3;
        int c = (task & 7) * 8;
        float4 a0 = make_float4(0.f, 0.f, 0.f, 0.f), a1 = a0;
        if (row < nrows) {
            int node = rowbase + row;
            long base = (long)node * HID + c;
            a0 = *(const float4*)&g_B1[base];
            a1 = *(const float4*)&g_B1[base + 4];
            int p = g_off[node], end = g_off[node + 1];
            for (; p + 2 <= end; p += 2) {
                int s0 = __ldg(&g_csr[p]);
                int s1 = __ldg(&g_csr[p + 1]);
                const float4* t0 = (const float4*)(g_B1 + (long)s0 * HID + c);
                const float4* t1 = (const float4*)(g_B1 + (long)s1 * HID + c);
                float4 v00 = __ldg(t0), v01 = __ldg(t0 + 1);
                float4 v10 = __ldg(t1), v11 = __ldg(t1 + 1);
                add4(a0, v00); add4(a1, v01);
                add4(a0, v10); add4(a1, v11);
            }
            if (p < end) {
                int s0 = __ldg(&g_csr[p]);
                const float4* t0 = (const float4*)(g_B1 + (long)s0 * HID + c);
                add4(a0, __ldg(t0)); add4(a1, __ldg(t0 + 1));
            }
            float4 bb0 = *(const float4*)&b1[c];
            float4 bb1 = *(const float4*)&b1[c + 4];
            a0.x = fmaxf(a0.x + bb0.x, 0.f); a0.y = fmaxf(a0.y + bb0.y, 0.f);
            a0.z = fmaxf(a0.z + bb0.z, 0.f); a0.w = fmaxf(a0.w + bb0.w, 0.f);
            a1.x = fmaxf(a1.x + bb1.x, 0.f); a1.y = fmaxf(a1.y + bb1.y, 0.f);
            a1.z = fmaxf(a1.z + bb1.z, 0.f); a1.w = fmaxf(a1.w + bb1.w, 0.f);
        }
        *(float4*)&u_sh[row * HID + c]     = a0;
        *(float4*)&u_sh[row * HID + c + 4] = a1;
    }
    __syncthreads();

    // phase 2: GEMM
    int rg = tid >> 3, cg = tid & 7;
    int r0 = rg * 8, c0 = cg * 8;
    float acc[8][8];
#pragma unroll
    for (int r = 0; r < 8; r++)
#pragma unroll
        for (int j = 0; j < 8; j++) acc[r][j] = 0.f;

    for (int k = 0; k < HID; k += 4) {
        float4 av[8];
#pragma unroll
        for (int r = 0; r < 8; r++)
            av[r] = *(const float4*)&u_sh[(r0 + r) * HID + k];
#pragma unroll
        for (int kk = 0; kk < 4; kk++) {
            float4 w0 = *(const float4*)&w_sh[(k + kk) * HID + c0];
            float4 w1 = *(const float4*)&w_sh[(k + kk) * HID + c0 + 4];
#pragma unroll
            for (int r = 0; r < 8; r++) {
                float a = (kk == 0) ? av[r].x : (kk == 1) ? av[r].y
                         : (kk == 2) ? av[r].z : av[r].w;
                acc[r][0] += a * w0.x; acc[r][1] += a * w0.y;
                acc[r][2] += a * w0.z; acc[r][3] += a * w0.w;
                acc[r][4] += a * w1.x; acc[r][5] += a * w1.y;
                acc[r][6] += a * w1.z; acc[r][7] += a * w1.w;
            }
        }
    }

    float4 bb0 = *(const float4*)&b2[c0];
    float4 bb1 = *(const float4*)&b2[c0 + 4];
    float ls[8] = {0,0,0,0,0,0,0,0};
    float lq[8] = {0,0,0,0,0,0,0,0};
#pragma unroll
    for (int r = 0; r < 8; r++) {
        if (r0 + r < nrows) {
            float o[8];
            o[0] = fmaxf(acc[r][0] + bb0.x, 0.f); o[1] = fmaxf(acc[r][1] + bb0.y, 0.f);
            o[2] = fmaxf(acc[r][2] + bb0.z, 0.f); o[3] = fmaxf(acc[r][3] + bb0.w, 0.f);
            o[4] = fmaxf(acc[r][4] + bb1.x, 0.f); o[5] = fmaxf(acc[r][5] + bb1.y, 0.f);
            o[6] = fmaxf(acc[r][6] + bb1.z, 0.f); o[7] = fmaxf(acc[r][7] + bb1.w, 0.f);
            long off = (long)(rowbase + r0 + r) * HID + c0;
            *(float4*)&g_B0[off]     = make_float4(o[0], o[1], o[2], o[3]);
            *(float4*)&g_B0[off + 4] = make_float4(o[4], o[5], o[6], o[7]);
#pragma unroll
            for (int j = 0; j < 8; j++) { ls[j] += o[j]; lq[j] += o[j] * o[j]; }
        }
    }
#pragma unroll
    for (int j = 0; j < 8; j++) {
        atomicAdd(&s_sum[c0 + j], ls[j]);
        atomicAdd(&s_sq[c0 + j],  lq[j]);
    }
    __syncthreads();
    float* stats = g_stats + layer * 2 * HID;
    if (tid < HID) {
        atomicAdd(&stats[tid], s_sum[tid]);
        atomicAdd(&stats[HID + tid], s_sq[tid]);
    }
}

// ---------------- pool: run-length segment max (batch is sorted) ------------
__global__ void __launch_bounds__(256) pool_kernel(
    const int* __restrict__ batch,
    const float* __restrict__ gamma, const float* __restrict__ beta)
{
    __shared__ float sc[HID], sf[HID];
    int tid = threadIdx.x;
    if (tid < HID) {
        const float* stats = g_stats + 2 * 2 * HID;   // layer 2
        float inv_n = 1.f / (float)N_NODES;
        float mu  = stats[tid] * inv_n;
        float var = stats[HID + tid] * inv_n - mu * mu;
        float s = gamma[tid] * rsqrtf(var + BN_EPS);
        sc[tid] = s;
        sf[tid] = beta[tid] - mu * s;
    }
    __syncthreads();

    int base = blockIdx.x * 128;
    int r = tid >> 6;       // 0..3
    int c = tid & 63;
    float cur = -INFINITY;
    int curg = -1;
    int lim = base + 128; if (lim > N_NODES) lim = N_NODES;
    for (int n = base + r; n < lim; n += 4) {
        int g = __ldg(&batch[n]);
        float v = g_B0[(long)n * HID + c] * sc[c] + sf[c];
        if (g != curg) {
            if (curg >= 0) atomicMaxF(&g_pooled[curg * HID + c], cur);
            curg = g; cur = v;
        } else {
            cur = fmaxf(cur, v);
        }
    }
    if (curg >= 0) atomicMaxF(&g_pooled[curg * HID + c], cur);
}

// ---------------- head: relu(pooled@lin1+b1)@lin2+b2 ------------------------
__global__ void __launch_bounds__(128) head_kernel(
    const float* __restrict__ lin1_w, const float* __restrict__ lin1_b,
    const float* __restrict__ lin2_w, const float* __restrict__ lin2_b,
    float* __restrict__ out)
{
    __shared__ float w1_sh[HID * HID];
    __shared__ float w2_sh[HID * OUT_F];
    __shared__ float p_sh[4][HID];
    __shared__ float h_sh[4][HID];
    int tid = threadIdx.x, warp = tid >> 5, lane = tid & 31;

    for (int i = tid; i < HID * HID / 4; i += 128)
        ((float4*)w1_sh)[i] = ((const float4*)lin1_w)[i];
    for (int i = tid; i < HID * OUT_F / 4; i += 128)
        ((float4*)w2_sh)[i] = ((const float4*)lin2_w)[i];

    int g = blockIdx.x * 4 + warp;
    float p0 = g_pooled[g * HID + lane];
    float p1 = g_pooled[g * HID + lane + 32];
    if (!isfinite(p0)) p0 = 0.f;
    if (!isfinite(p1)) p1 = 0.f;
    p_sh[warp][lane] = p0;
    p_sh[warp][lane + 32] = p1;
    __syncthreads();

    float acc0 = lin1_b[lane], acc1 = lin1_b[lane + 32];
#pragma unroll 8
    for (int k = 0; k < HID; k++) {
        float pv = p_sh[warp][k];
        acc0 += pv * w1_sh[k * HID + lane];
        acc1 += pv * w1_sh[k * HID + lane + 32];
    }
    h_sh[warp][lane]      = fmaxf(acc0, 0.f);
    h_sh[warp][lane + 32] = fmaxf(acc1, 0.f);
    __syncwarp();

    if (lane < OUT_F) {
        float acc = lin2_b[lane];
#pragma unroll 8
        for (int k = 0; k < HID; k++)
            acc += h_sh[warp][k] * w2_sh[k * OUT_F + lane];
        out[g * OUT_F + lane] = acc;
    }
}

// ---------------- launch ----------------------------------------------------
extern "C" void kernel_launch(void* const* d_in, const int* in_sizes, int n_in,
                              void* d_out, int out_size)
{
    const float* x     = (const float*)d_in[0];
    const int*   ei    = (const int*)d_in[1];    // int32 (JAX x64 disabled)
    const int*   batch = (const int*)d_in[2];
    const float* l0_w1 = (const float*)d_in[3];
    const float* l0_b1 = (const float*)d_in[4];
    const float* l0_w2 = (const float*)d_in[5];
    const float* l0_b2 = (const float*)d_in[6];
    const float* l0_g  = (const float*)d_in[7];
    const float* l0_be = (const float*)d_in[8];
    const float* ws1   = (const float*)d_in[9];
    const float* bs1   = (const float*)d_in[10];
    const float* ws2   = (const float*)d_in[11];
    const float* bs2   = (const float*)d_in[12];
    const float* gms   = (const float*)d_in[13];
    const float* bts   = (const float*)d_in[14];
    const float* lin1w = (const float*)d_in[15];
    const float* lin1b = (const float*)d_in[16];
    const float* lin2w = (const float*)d_in[17];
    const float* lin2b = (const float*)d_in[18];
    float* out = (float*)d_out;

    const int GEMM_BLOCKS = (N_NODES + 127) / 128;     // 391
    const int EDGE_BLOCKS = (N_EDGES + 255) / 256;     // 3125

    const int SMEM_G1_L0 = (F_INPUT * HID + 128 * F_INPUT) * 4;  // 96 KB
    const int SMEM_G1_LN = (HID * HID + 128 * HID) * 4;          // 48 KB
    const int SMEM_AG2   = (HID * HID + 128 * HID) * 4;          // 48 KB
    cudaFuncSetAttribute(gemm1_kernel<F_INPUT, false>,
                         cudaFuncAttributeMaxDynamicSharedMemorySize, SMEM_G1_L0);
    cudaFuncSetAttribute(gemm1_kernel<HID, true>,
                         cudaFuncAttributeMaxDynamicSharedMemorySize, SMEM_G1_LN);
    cudaFuncSetAttribute(agg_gemm2_kernel,
                         cudaFuncAttributeMaxDynamicSharedMemorySize, SMEM_AG2);

    // ---- init + CSR build (reused by all 3 layers) ----
    init_kernel<<<(N_GRAPHS * HID + 255) / 256, 256>>>();
    hist_kernel<<<EDGE_BLOCKS, 256>>>(ei);
    scanA_kernel<<<NBLK256, 256>>>();
    scanB_kernel<<<1, 256>>>();
    scanC_kernel<<<NBLK256, 256>>>();
    fill_kernel<<<EDGE_BLOCKS, 256>>>(ei);

    // ---- layer 0 (128 -> 64) ----
    gemm1_kernel<F_INPUT, false><<<GEMM_BLOCKS, 128, SMEM_G1_L0>>>(
        x, l0_w1, nullptr, nullptr, 0);
    agg_gemm2_kernel<<<GEMM_BLOCKS, 128, SMEM_AG2>>>(l0_b1, l0_w2, l0_b2, 0);

    // ---- layer 1 (64 -> 64), folds layer-0 BN into weights inline ----
    gemm1_kernel<HID, true><<<GEMM_BLOCKS, 128, SMEM_G1_LN>>>(
        nullptr, ws1, l0_g, l0_be, 0);
    agg_gemm2_kernel<<<GEMM_BLOCKS, 128, SMEM_AG2>>>(bs1, ws2, bs2, 1);

    // ---- layer 2 (64 -> 64), folds layer-1 BN inline ----
    gemm1_kernel<HID, true><<<GEMM_BLOCKS, 128, SMEM_G1_LN>>>(
        nullptr, ws1 + HID * HID, gms, bts, 1);
    agg_gemm2_kernel<<<GEMM_BLOCKS, 128, SMEM_AG2>>>(
        bs1 + HID, ws2 + HID * HID, bs2 + HID, 2);

    // ---- pool (computes layer-2 BN inline) + head ----
    pool_kernel<<<GEMM_BLOCKS, 256>>>(batch, gms + HID, bts + HID);
    head_kernel<<<N_GRAPHS / 4, 128>>>(lin1w, lin1b, lin2w, lin2b, out);
}